// round 2
// baseline (speedup 1.0000x reference)
#include <cuda_runtime.h>
#include <math.h>

#define BATCH 8
#define SEQ 1024
#define DIM 512
#define HEADS 16
#define HD 32
#define MROWS (BATCH*SEQ)   /* 8192 */
#define MLPH 2048

// ---------------- scratch (device globals; no allocations allowed) ----------
__device__ float g_h[MROWS * DIM];           // LN1 out, reused for LN2 out
__device__ float g_qkv[MROWS * 3 * DIM];     // [row, 1536]: q|k|v
__device__ float g_bias[HEADS * SEQ * SEQ];  // [h][l][m] expanded rel-pos bias
__device__ float g_attnout[MROWS * DIM];     // [B,L,C] attention output
__device__ float g_xres[MROWS * DIM];        // x + proj(attn)
__device__ float g_mlp1[MROWS * MLPH];       // gelu(fc1)

// ---------------- LayerNorm: one block per row of 512 ----------------------
__global__ void __launch_bounds__(128) ln_kernel(const float* __restrict__ x,
                                                 const float* __restrict__ g,
                                                 const float* __restrict__ b,
                                                 float* __restrict__ out)
{
    const int row = blockIdx.x;
    const int t = threadIdx.x;
    const float4 v = ((const float4*)(x + (size_t)row * DIM))[t];
    float s  = v.x + v.y + v.z + v.w;
    float s2 = v.x*v.x + v.y*v.y + v.z*v.z + v.w*v.w;
    #pragma unroll
    for (int o = 16; o > 0; o >>= 1) {
        s  += __shfl_xor_sync(0xffffffffu, s,  o);
        s2 += __shfl_xor_sync(0xffffffffu, s2, o);
    }
    __shared__ float rs[4], rs2[4];
    if ((t & 31) == 0) { rs[t >> 5] = s; rs2[t >> 5] = s2; }
    __syncthreads();
    s  = rs[0] + rs[1] + rs[2] + rs[3];
    s2 = rs2[0] + rs2[1] + rs2[2] + rs2[3];
    const float mean = s * (1.0f / DIM);
    const float var  = s2 * (1.0f / DIM) - mean * mean;
    const float inv  = rsqrtf(var + 1e-5f);
    const float4 gg = ((const float4*)g)[t];
    const float4 bb = ((const float4*)b)[t];
    float4 o4;
    o4.x = (v.x - mean) * inv * gg.x + bb.x;
    o4.y = (v.y - mean) * inv * gg.y + bb.y;
    o4.z = (v.z - mean) * inv * gg.z + bb.z;
    o4.w = (v.w - mean) * inv * gg.w + bb.w;
    ((float4*)(out + (size_t)row * DIM))[t] = o4;
}

// ---------------- bias expand: g_bias[h][l][m] = table[rel[l][m]*16+h] ------
__global__ void __launch_bounds__(256) bias_expand_kernel(const int* __restrict__ rel,
                                                          const float* __restrict__ table)
{
    const unsigned idx = blockIdx.x * 256u + threadIdx.x;   // < 16*1024*1024
    const int m = idx & 1023;
    const int l = (idx >> 10) & 1023;
    const int h = idx >> 20;
    const int ri = rel[l * SEQ + m];
    g_bias[idx] = table[ri * HEADS + h];
}

// ---------------- SGEMM: 128x128 tile, BK=16, 8x8 per thread ----------------
// C[M,N] = epilogue(A[M,K] @ W[K,N] + bias [, R])
enum { EPI_BIAS = 0, EPI_GELU = 1, EPI_RES = 2 };

template <int EPI>
__global__ void __launch_bounds__(256) gemm_kernel(const float* __restrict__ A,
                                                   const float* __restrict__ W,
                                                   const float* __restrict__ bias,
                                                   const float* __restrict__ R,
                                                   float* __restrict__ C,
                                                   int M, int N, int K)
{
    __shared__ float As[16][128];
    __shared__ float Bs[16][128];
    const int bm = blockIdx.y * 128, bn = blockIdx.x * 128;
    const int tid = threadIdx.x;
    const int tx = tid & 15, ty = tid >> 4;
    const int arow = tid >> 2, ac = (tid & 3) * 4;   // A tile: 128 rows x 16 cols
    const int brow = tid >> 5, bc = (tid & 31) * 4;  // B tile: 16 rows x 128 cols

    float acc[8][8] = {};
    float4 pa[2], pb[2];
    #pragma unroll
    for (int l = 0; l < 2; l++) {
        pa[l] = *(const float4*)(A + (size_t)(bm + arow + l * 64) * K + ac);
        pb[l] = *(const float4*)(W + (size_t)(brow + l * 8) * N + bn + bc);
    }
    const int nk = K >> 4;
    for (int kt = 0; kt < nk; kt++) {
        #pragma unroll
        for (int l = 0; l < 2; l++) {
            const int r = arow + l * 64;
            As[ac + 0][r] = pa[l].x;
            As[ac + 1][r] = pa[l].y;
            As[ac + 2][r] = pa[l].z;
            As[ac + 3][r] = pa[l].w;
            *(float4*)&Bs[brow + l * 8][bc] = pb[l];
        }
        __syncthreads();
        if (kt + 1 < nk) {
            const int k0 = (kt + 1) * 16;
            #pragma unroll
            for (int l = 0; l < 2; l++) {
                pa[l] = *(const float4*)(A + (size_t)(bm + arow + l * 64) * K + k0 + ac);
                pb[l] = *(const float4*)(W + (size_t)(k0 + brow + l * 8) * N + bn + bc);
            }
        }
        #pragma unroll
        for (int k = 0; k < 16; k++) {
            float a[8], bv[8];
            *(float4*)&a[0]  = *(const float4*)&As[k][ty * 8];
            *(float4*)&a[4]  = *(const float4*)&As[k][ty * 8 + 4];
            *(float4*)&bv[0] = *(const float4*)&Bs[k][tx * 8];
            *(float4*)&bv[4] = *(const float4*)&Bs[k][tx * 8 + 4];
            #pragma unroll
            for (int i = 0; i < 8; i++)
                #pragma unroll
                for (int j = 0; j < 8; j++)
                    acc[i][j] += a[i] * bv[j];
        }
        __syncthreads();
    }
    // epilogue
    float bvv[8];
    *(float4*)&bvv[0] = *(const float4*)(bias + bn + tx * 8);
    *(float4*)&bvv[4] = *(const float4*)(bias + bn + tx * 8 + 4);
    #pragma unroll
    for (int i = 0; i < 8; i++) {
        const size_t row = (size_t)(bm + ty * 8 + i);
        #pragma unroll
        for (int j0 = 0; j0 < 8; j0 += 4) {
            float4 o;
            float* oo = &o.x;
            #pragma unroll
            for (int jj = 0; jj < 4; jj++) {
                float c = acc[i][j0 + jj] + bvv[j0 + jj];
                if (EPI == EPI_GELU)
                    c = 0.5f * c * (1.0f + erff(c * 0.70710678118654752f));
                oo[jj] = c;
            }
            const size_t off = row * N + bn + tx * 8 + j0;
            if (EPI == EPI_RES) {
                const float4 r4 = *(const float4*)(R + off);
                o.x += r4.x; o.y += r4.y; o.z += r4.z; o.w += r4.w;
            }
            *(float4*)(C + off) = o;
        }
    }
}

// ---------------- Flash attention: 1 query/thread, 32-key tiles -------------
// grid (8 qtiles, 16 heads, 8 batch), 128 threads
__global__ void __launch_bounds__(128) attn_kernel(float* __restrict__ out)
{
    const int b = blockIdx.z, h = blockIdx.y, q0 = blockIdx.x * 128;
    const int t = threadIdx.x;
    const int l = q0 + t;

    __shared__ float Ks[32][32];
    __shared__ float Vs[32][32];
    __shared__ float Bsm[128][33];   // padded -> conflict-free [t][j] reads

    const float scale = 0.17677669529663687f;  // 1/sqrt(32)
    float q[32];
    {
        const float* qp = g_qkv + ((size_t)(b * SEQ + l)) * (3 * DIM) + h * HD;
        #pragma unroll
        for (int d4 = 0; d4 < 8; d4++) {
            const float4 v = *(const float4*)(qp + d4 * 4);
            q[d4 * 4 + 0] = v.x * scale;
            q[d4 * 4 + 1] = v.y * scale;
            q[d4 * 4 + 2] = v.z * scale;
            q[d4 * 4 + 3] = v.w * scale;
        }
    }
    float mi = -1e30f, li = 0.0f;
    float acc[32];
    #pragma unroll
    for (int d = 0; d < 32; d++) acc[d] = 0.0f;

    const float* bb = g_bias + ((size_t)h * SEQ + q0) * SEQ;

    for (int m0 = 0; m0 < SEQ; m0 += 32) {
        __syncthreads();
        // K,V tiles: 32 rows x 32 floats each = 256 float4 each
        #pragma unroll
        for (int l2 = 0; l2 < 2; l2++) {
            const int fid = t + l2 * 128;
            const int r = fid >> 3, c4 = fid & 7;
            const float* kp = g_qkv + ((size_t)(b * SEQ + m0 + r)) * (3 * DIM) + DIM + h * HD + c4 * 4;
            *(float4*)&Ks[r][c4 * 4] = *(const float4*)kp;
            *(float4*)&Vs[r][c4 * 4] = *(const float4*)(kp + DIM);
        }
        // bias tile: 128 rows x 32 floats = 1024 float4
        #pragma unroll
        for (int l2 = 0; l2 < 8; l2++) {
            const int fid = t + l2 * 128;
            const int r = fid >> 3, c4 = fid & 7;
            const float4 v = *(const float4*)(bb + (size_t)r * SEQ + m0 + c4 * 4);
            Bsm[r][c4 * 4 + 0] = v.x;
            Bsm[r][c4 * 4 + 1] = v.y;
            Bsm[r][c4 * 4 + 2] = v.z;
            Bsm[r][c4 * 4 + 3] = v.w;
        }
        __syncthreads();

        float s[32];
        float tmax = mi;
        #pragma unroll
        for (int j = 0; j < 32; j++) {
            float sum = 0.0f;
            #pragma unroll
            for (int d4 = 0; d4 < 8; d4++) {
                const float4 kv = *(const float4*)&Ks[j][d4 * 4];
                sum += q[d4 * 4 + 0] * kv.x;
                sum += q[d4 * 4 + 1] * kv.y;
                sum += q[d4 * 4 + 2] * kv.z;
                sum += q[d4 * 4 + 3] * kv.w;
            }
            sum += Bsm[t][j];
            s[j] = sum;
            tmax = fmaxf(tmax, sum);
        }
        const float corr = __expf(mi - tmax);
        mi = tmax;
        li *= corr;
        #pragma unroll
        for (int d = 0; d < 32; d++) acc[d] *= corr;
        #pragma unroll
        for (int j = 0; j < 32; j++) {
            const float p = __expf(s[j] - mi);
            li += p;
            #pragma unroll
            for (int d4 = 0; d4 < 8; d4++) {
                const float4 vv = *(const float4*)&Vs[j][d4 * 4];
                acc[d4 * 4 + 0] += p * vv.x;
                acc[d4 * 4 + 1] += p * vv.y;
                acc[d4 * 4 + 2] += p * vv.z;
                acc[d4 * 4 + 3] += p * vv.w;
            }
        }
    }
    const float inv = 1.0f / li;
    float* op = out + ((size_t)(b * SEQ + l)) * DIM + h * HD;
    #pragma unroll
    for (int d4 = 0; d4 < 8; d4++) {
        float4 o;
        o.x = acc[d4 * 4 + 0] * inv;
        o.y = acc[d4 * 4 + 1] * inv;
        o.z = acc[d4 * 4 + 2] * inv;
        o.w = acc[d4 * 4 + 3] * inv;
        *(float4*)(op + d4 * 4) = o;
    }
}

// ---------------- launch -----------------------------------------------------
extern "C" void kernel_launch(void* const* d_in, const int* in_sizes, int n_in,
                              void* d_out, int out_size)
{
    const float* x      = (const float*)d_in[0];
    const int*   rel    = (const int*)  d_in[1];
    const float* table  = (const float*)d_in[2];
    const float* qkv_w  = (const float*)d_in[3];
    const float* qkv_b  = (const float*)d_in[4];
    const float* proj_w = (const float*)d_in[5];
    const float* proj_b = (const float*)d_in[6];
    const float* n1_g   = (const float*)d_in[7];
    const float* n1_b   = (const float*)d_in[8];
    const float* n2_g   = (const float*)d_in[9];
    const float* n2_b   = (const float*)d_in[10];
    const float* fc1_w  = (const float*)d_in[11];
    const float* fc1_b  = (const float*)d_in[12];
    const float* fc2_w  = (const float*)d_in[13];
    const float* fc2_b  = (const float*)d_in[14];
    float* out = (float*)d_out;

    float *h, *qkv, *attnout, *xres, *mlp1;
    cudaGetSymbolAddress((void**)&h,       g_h);
    cudaGetSymbolAddress((void**)&qkv,     g_qkv);
    cudaGetSymbolAddress((void**)&attnout, g_attnout);
    cudaGetSymbolAddress((void**)&xres,    g_xres);
    cudaGetSymbolAddress((void**)&mlp1,    g_mlp1);

    // 1. h = LN1(x)
    ln_kernel<<<MROWS, 128>>>(x, n1_g, n1_b, h);
    // 2. qkv = h @ qkv_w + qkv_b        [8192, 1536]
    gemm_kernel<EPI_BIAS><<<dim3(12, 64), 256>>>(h, qkv_w, qkv_b, nullptr, qkv,
                                                 MROWS, 3 * DIM, DIM);
    // 3. expand rel-pos bias to [H, L, L]
    bias_expand_kernel<<<(HEADS * SEQ * SEQ) / 256, 256>>>(rel, table);
    // 4. flash attention -> [B, L, C]
    attn_kernel<<<dim3(8, HEADS, BATCH), 128>>>(attnout);
    // 5. xres = x + attnout @ proj_w + proj_b
    gemm_kernel<EPI_RES><<<dim3(4, 64), 256>>>(attnout, proj_w, proj_b, x, xres,
                                               MROWS, DIM, DIM);
    // 6. h = LN2(xres)
    ln_kernel<<<MROWS, 128>>>(xres, n2_g, n2_b, h);
    // 7. mlp1 = gelu(h @ fc1_w + fc1_b)  [8192, 2048]
    gemm_kernel<EPI_GELU><<<dim3(16, 64), 256>>>(h, fc1_w, fc1_b, nullptr, mlp1,
                                                 MROWS, MLPH, DIM);
    // 8. out = xres + mlp1 @ fc2_w + fc2_b
    gemm_kernel<EPI_RES><<<dim3(4, 64), 256>>>(mlp1, fc2_w, fc2_b, xres, out,
                                               MROWS, DIM, MLPH);
}

// round 3
// speedup vs baseline: 1.6760x; 1.6760x over previous
#include <cuda_runtime.h>
#include <math.h>
#include <stdint.h>

#define BATCH 8
#define SEQ 1024
#define DIM 512
#define HEADS 16
#define HD 32
#define MROWS (BATCH*SEQ)   /* 8192 */
#define MLPH 2048

// ---------------- scratch (device globals; no allocations allowed) ----------
__device__ float g_h[MROWS * DIM];           // LN1 out, reused for LN2 out
__device__ float g_qkv[MROWS * 3 * DIM];     // [row, 1536]: q|k|v
__device__ float g_bias[HEADS * SEQ * SEQ];  // [h][l][m] expanded rel-pos bias
__device__ float g_attnout[MROWS * DIM];     // [B,L,C] attention output
__device__ float g_xres[MROWS * DIM];        // x + proj(attn)
__device__ float g_mlp1[MROWS * MLPH];       // gelu(fc1)

// ---------------- LayerNorm: one block per row of 512 ----------------------
__global__ void __launch_bounds__(128) ln_kernel(const float* __restrict__ x,
                                                 const float* __restrict__ g,
                                                 const float* __restrict__ b,
                                                 float* __restrict__ out)
{
    const int row = blockIdx.x;
    const int t = threadIdx.x;
    const float4 v = ((const float4*)(x + (size_t)row * DIM))[t];
    float s  = v.x + v.y + v.z + v.w;
    float s2 = v.x*v.x + v.y*v.y + v.z*v.z + v.w*v.w;
    #pragma unroll
    for (int o = 16; o > 0; o >>= 1) {
        s  += __shfl_xor_sync(0xffffffffu, s,  o);
        s2 += __shfl_xor_sync(0xffffffffu, s2, o);
    }
    __shared__ float rs[4], rs2[4];
    if ((t & 31) == 0) { rs[t >> 5] = s; rs2[t >> 5] = s2; }
    __syncthreads();
    s  = rs[0] + rs[1] + rs[2] + rs[3];
    s2 = rs2[0] + rs2[1] + rs2[2] + rs2[3];
    const float mean = s * (1.0f / DIM);
    const float var  = s2 * (1.0f / DIM) - mean * mean;
    const float inv  = rsqrtf(var + 1e-5f);
    const float4 gg = ((const float4*)g)[t];
    const float4 bb = ((const float4*)b)[t];
    float4 o4;
    o4.x = (v.x - mean) * inv * gg.x + bb.x;
    o4.y = (v.y - mean) * inv * gg.y + bb.y;
    o4.z = (v.z - mean) * inv * gg.z + bb.z;
    o4.w = (v.w - mean) * inv * gg.w + bb.w;
    ((float4*)(out + (size_t)row * DIM))[t] = o4;
}

// ---------------- bias expand: g_bias[h][l][m] = table[rel[l][m]*16+h] ------
__global__ void __launch_bounds__(256) bias_expand_kernel(const int* __restrict__ rel,
                                                          const float* __restrict__ table)
{
    const unsigned idx = blockIdx.x * 256u + threadIdx.x;   // < 16*1024*1024
    const int m = idx & 1023;
    const int l = (idx >> 10) & 1023;
    const int h = idx >> 20;
    const int ri = rel[l * SEQ + m];
    g_bias[idx] = table[ri * HEADS + h];
}

// ---------------- tf32 tensor-core GEMM ------------------------------------
// C[M,N] = epilogue(A[M,K] @ W[K,N] + bias [, R])
// 128x128 block tile, BK=32, 256 threads = 8 warps (4x2), warp tile 32x64.
// m16n8k8 tf32 mma, fp32 accumulate. Inputs rounded to tf32 via cvt.rna.
enum { EPI_BIAS = 0, EPI_GELU = 1, EPI_RES = 2 };

__device__ __forceinline__ float to_tf32(float x) {
    uint32_t u;
    asm("cvt.rna.tf32.f32 %0, %1;" : "=r"(u) : "f"(x));
    return __uint_as_float(u);
}

__device__ __forceinline__ void mma_tf32(float* c, const uint32_t* a,
                                         uint32_t b0, uint32_t b1) {
    asm volatile(
        "mma.sync.aligned.m16n8k8.row.col.f32.tf32.tf32.f32 "
        "{%0,%1,%2,%3}, {%4,%5,%6,%7}, {%8,%9}, {%0,%1,%2,%3};"
        : "+f"(c[0]), "+f"(c[1]), "+f"(c[2]), "+f"(c[3])
        : "r"(a[0]), "r"(a[1]), "r"(a[2]), "r"(a[3]), "r"(b0), "r"(b1));
}

template <int EPI>
__global__ void __launch_bounds__(256) gemm_tc(const float* __restrict__ A,
                                               const float* __restrict__ W,
                                               const float* __restrict__ bias,
                                               const float* __restrict__ R,
                                               float* __restrict__ C,
                                               int M, int N, int K)
{
    __shared__ float As[128][36];   // [m][k], stride 36 -> frag LDS conflict-free
    __shared__ float Bs[32][136];   // [k][n], stride 136 -> frag LDS conflict-free

    const int bm = blockIdx.y * 128, bn = blockIdx.x * 128;
    const int tid = threadIdx.x;
    const int warp = tid >> 5, lane = tid & 31;
    const int wm = (warp & 3) * 32, wn = (warp >> 2) * 64;
    const int g = lane >> 2, t4 = lane & 3;

    float4 pa[4], pb[4];
    #pragma unroll
    for (int i = 0; i < 4; i++) {
        const int ia = tid + i * 256;                 // A: m = ia>>3, c4 = ia&7
        pa[i] = *(const float4*)(A + (size_t)(bm + (ia >> 3)) * K + (ia & 7) * 4);
        const int ib = tid + i * 256;                 // B: k = ib>>5, c4 = ib&31
        pb[i] = *(const float4*)(W + (size_t)(ib >> 5) * N + bn + (ib & 31) * 4);
    }

    float acc[2][8][4];
    #pragma unroll
    for (int mi = 0; mi < 2; mi++)
        #pragma unroll
        for (int ni = 0; ni < 8; ni++)
            #pragma unroll
            for (int c = 0; c < 4; c++) acc[mi][ni][c] = 0.0f;

    const int nk = K >> 5;
    for (int kt = 0; kt < nk; kt++) {
        #pragma unroll
        for (int i = 0; i < 4; i++) {
            const int ia = tid + i * 256;
            float4 va = pa[i];
            va.x = to_tf32(va.x); va.y = to_tf32(va.y);
            va.z = to_tf32(va.z); va.w = to_tf32(va.w);
            *(float4*)&As[ia >> 3][(ia & 7) * 4] = va;
            const int ib = tid + i * 256;
            float4 vb = pb[i];
            vb.x = to_tf32(vb.x); vb.y = to_tf32(vb.y);
            vb.z = to_tf32(vb.z); vb.w = to_tf32(vb.w);
            *(float4*)&Bs[ib >> 5][(ib & 31) * 4] = vb;
        }
        __syncthreads();
        if (kt + 1 < nk) {
            const int k0 = (kt + 1) * 32;
            #pragma unroll
            for (int i = 0; i < 4; i++) {
                const int ia = tid + i * 256;
                pa[i] = *(const float4*)(A + (size_t)(bm + (ia >> 3)) * K + k0 + (ia & 7) * 4);
                const int ib = tid + i * 256;
                pb[i] = *(const float4*)(W + (size_t)(k0 + (ib >> 5)) * N + bn + (ib & 31) * 4);
            }
        }
        #pragma unroll
        for (int ks = 0; ks < 4; ks++) {
            const int kk = ks * 8;
            uint32_t af[2][4];
            #pragma unroll
            for (int mi = 0; mi < 2; mi++) {
                const int rm = wm + mi * 16;
                af[mi][0] = __float_as_uint(As[rm + g][kk + t4]);
                af[mi][1] = __float_as_uint(As[rm + g + 8][kk + t4]);
                af[mi][2] = __float_as_uint(As[rm + g][kk + t4 + 4]);
                af[mi][3] = __float_as_uint(As[rm + g + 8][kk + t4 + 4]);
            }
            #pragma unroll
            for (int ni = 0; ni < 8; ni++) {
                const int cn = wn + ni * 8 + g;
                const uint32_t b0 = __float_as_uint(Bs[kk + t4][cn]);
                const uint32_t b1 = __float_as_uint(Bs[kk + t4 + 4][cn]);
                mma_tf32(acc[0][ni], af[0], b0, b1);
                mma_tf32(acc[1][ni], af[1], b0, b1);
            }
        }
        __syncthreads();
    }

    // epilogue: c0,c1 at (row, col), (row, col+1); c2,c3 at (row+8, ...)
    #pragma unroll
    for (int mi = 0; mi < 2; mi++) {
        const int r0 = bm + wm + mi * 16 + g;
        #pragma unroll
        for (int ni = 0; ni < 8; ni++) {
            const int col = bn + wn + ni * 8 + t4 * 2;
            const float b0 = bias[col], b1 = bias[col + 1];
            float v[4];
            v[0] = acc[mi][ni][0] + b0;
            v[1] = acc[mi][ni][1] + b1;
            v[2] = acc[mi][ni][2] + b0;
            v[3] = acc[mi][ni][3] + b1;
            if (EPI == EPI_GELU) {
                #pragma unroll
                for (int c = 0; c < 4; c++)
                    v[c] = 0.5f * v[c] * (1.0f + erff(v[c] * 0.70710678118654752f));
            }
            const size_t off0 = (size_t)r0 * N + col;
            const size_t off1 = (size_t)(r0 + 8) * N + col;
            float2 o0 = make_float2(v[0], v[1]);
            float2 o1 = make_float2(v[2], v[3]);
            if (EPI == EPI_RES) {
                const float2 r4a = *(const float2*)(R + off0);
                const float2 r4b = *(const float2*)(R + off1);
                o0.x += r4a.x; o0.y += r4a.y;
                o1.x += r4b.x; o1.y += r4b.y;
            }
            *(float2*)(C + off0) = o0;
            *(float2*)(C + off1) = o1;
        }
    }
}

// ---------------- Flash attention: 1 query/thread, 32-key tiles -------------
// grid (8 qtiles, 16 heads, 8 batch), 128 threads
__global__ void __launch_bounds__(128) attn_kernel(float* __restrict__ out)
{
    const int b = blockIdx.z, h = blockIdx.y, q0 = blockIdx.x * 128;
    const int t = threadIdx.x;
    const int l = q0 + t;

    __shared__ float Ks[32][32];
    __shared__ float Vs[32][32];
    __shared__ float Bsm[128][33];   // padded -> conflict-free [t][j] reads

    const float scale = 0.17677669529663687f;  // 1/sqrt(32)
    float q[32];
    {
        const float* qp = g_qkv + ((size_t)(b * SEQ + l)) * (3 * DIM) + h * HD;
        #pragma unroll
        for (int d4 = 0; d4 < 8; d4++) {
            const float4 v = *(const float4*)(qp + d4 * 4);
            q[d4 * 4 + 0] = v.x * scale;
            q[d4 * 4 + 1] = v.y * scale;
            q[d4 * 4 + 2] = v.z * scale;
            q[d4 * 4 + 3] = v.w * scale;
        }
    }
    float mi = -1e30f, li = 0.0f;
    float acc[32];
    #pragma unroll
    for (int d = 0; d < 32; d++) acc[d] = 0.0f;

    const float* bb = g_bias + ((size_t)h * SEQ + q0) * SEQ;

    for (int m0 = 0; m0 < SEQ; m0 += 32) {
        __syncthreads();
        #pragma unroll
        for (int l2 = 0; l2 < 2; l2++) {
            const int fid = t + l2 * 128;
            const int r = fid >> 3, c4 = fid & 7;
            const float* kp = g_qkv + ((size_t)(b * SEQ + m0 + r)) * (3 * DIM) + DIM + h * HD + c4 * 4;
            *(float4*)&Ks[r][c4 * 4] = *(const float4*)kp;
            *(float4*)&Vs[r][c4 * 4] = *(const float4*)(kp + DIM);
        }
        #pragma unroll
        for (int l2 = 0; l2 < 8; l2++) {
            const int fid = t + l2 * 128;
            const int r = fid >> 3, c4 = fid & 7;
            const float4 v = *(const float4*)(bb + (size_t)r * SEQ + m0 + c4 * 4);
            Bsm[r][c4 * 4 + 0] = v.x;
            Bsm[r][c4 * 4 + 1] = v.y;
            Bsm[r][c4 * 4 + 2] = v.z;
            Bsm[r][c4 * 4 + 3] = v.w;
        }
        __syncthreads();

        float s[32];
        float tmax = mi;
        #pragma unroll
        for (int j = 0; j < 32; j++) {
            float sum = 0.0f;
            #pragma unroll
            for (int d4 = 0; d4 < 8; d4++) {
                const float4 kv = *(const float4*)&Ks[j][d4 * 4];
                sum += q[d4 * 4 + 0] * kv.x;
                sum += q[d4 * 4 + 1] * kv.y;
                sum += q[d4 * 4 + 2] * kv.z;
                sum += q[d4 * 4 + 3] * kv.w;
            }
            sum += Bsm[t][j];
            s[j] = sum;
            tmax = fmaxf(tmax, sum);
        }
        const float corr = __expf(mi - tmax);
        mi = tmax;
        li *= corr;
        #pragma unroll
        for (int d = 0; d < 32; d++) acc[d] *= corr;
        #pragma unroll
        for (int j = 0; j < 32; j++) {
            const float p = __expf(s[j] - mi);
            li += p;
            #pragma unroll
            for (int d4 = 0; d4 < 8; d4++) {
                const float4 vv = *(const float4*)&Vs[j][d4 * 4];
                acc[d4 * 4 + 0] += p * vv.x;
                acc[d4 * 4 + 1] += p * vv.y;
                acc[d4 * 4 + 2] += p * vv.z;
                acc[d4 * 4 + 3] += p * vv.w;
            }
        }
    }
    const float inv = 1.0f / li;
    float* op = out + ((size_t)(b * SEQ + l)) * DIM + h * HD;
    #pragma unroll
    for (int d4 = 0; d4 < 8; d4++) {
        float4 o;
        o.x = acc[d4 * 4 + 0] * inv;
        o.y = acc[d4 * 4 + 1] * inv;
        o.z = acc[d4 * 4 + 2] * inv;
        o.w = acc[d4 * 4 + 3] * inv;
        *(float4*)(op + d4 * 4) = o;
    }
}

// ---------------- launch -----------------------------------------------------
extern "C" void kernel_launch(void* const* d_in, const int* in_sizes, int n_in,
                              void* d_out, int out_size)
{
    const float* x      = (const float*)d_in[0];
    const int*   rel    = (const int*)  d_in[1];
    const float* table  = (const float*)d_in[2];
    const float* qkv_w  = (const float*)d_in[3];
    const float* qkv_b  = (const float*)d_in[4];
    const float* proj_w = (const float*)d_in[5];
    const float* proj_b = (const float*)d_in[6];
    const float* n1_g   = (const float*)d_in[7];
    const float* n1_b   = (const float*)d_in[8];
    const float* n2_g   = (const float*)d_in[9];
    const float* n2_b   = (const float*)d_in[10];
    const float* fc1_w  = (const float*)d_in[11];
    const float* fc1_b  = (const float*)d_in[12];
    const float* fc2_w  = (const float*)d_in[13];
    const float* fc2_b  = (const float*)d_in[14];
    float* out = (float*)d_out;

    float *h, *qkv, *attnout, *xres, *mlp1;
    cudaGetSymbolAddress((void**)&h,       g_h);
    cudaGetSymbolAddress((void**)&qkv,     g_qkv);
    cudaGetSymbolAddress((void**)&attnout, g_attnout);
    cudaGetSymbolAddress((void**)&xres,    g_xres);
    cudaGetSymbolAddress((void**)&mlp1,    g_mlp1);

    // 1. h = LN1(x)
    ln_kernel<<<MROWS, 128>>>(x, n1_g, n1_b, h);
    // 2. qkv = h @ qkv_w + qkv_b        [8192, 1536]
    gemm_tc<EPI_BIAS><<<dim3(12, 64), 256>>>(h, qkv_w, qkv_b, nullptr, qkv,
                                             MROWS, 3 * DIM, DIM);
    // 3. expand rel-pos bias to [H, L, L]
    bias_expand_kernel<<<(HEADS * SEQ * SEQ) / 256, 256>>>(rel, table);
    // 4. flash attention -> [B, L, C]
    attn_kernel<<<dim3(8, HEADS, BATCH), 128>>>(attnout);
    // 5. xres = x + attnout @ proj_w + proj_b
    gemm_tc<EPI_RES><<<dim3(4, 64), 256>>>(attnout, proj_w, proj_b, x, xres,
                                           MROWS, DIM, DIM);
    // 6. h = LN2(xres)
    ln_kernel<<<MROWS, 128>>>(xres, n2_g, n2_b, h);
    // 7. mlp1 = gelu(h @ fc1_w + fc1_b)  [8192, 2048]
    gemm_tc<EPI_GELU><<<dim3(16, 64), 256>>>(h, fc1_w, fc1_b, nullptr, mlp1,
                                             MROWS, MLPH, DIM);
    // 8. out = xres + mlp1 @ fc2_w + fc2_b
    gemm_tc<EPI_RES><<<dim3(4, 64), 256>>>(mlp1, fc2_w, fc2_b, xres, out,
                                           MROWS, DIM, MLPH);
}

// round 4
// speedup vs baseline: 2.3101x; 1.3783x over previous
#include <cuda_runtime.h>
#include <math.h>
#include <stdint.h>

#define BATCH 8
#define SEQ 1024
#define DIM 512
#define HEADS 16
#define HD 32
#define MROWS (BATCH*SEQ)   /* 8192 */
#define MLPH 2048

// ---------------- scratch (device globals; no allocations allowed) ----------
__device__ float g_h[MROWS * DIM];           // LN1 out, reused for LN2 out
__device__ float g_qkv[MROWS * 3 * DIM];     // [row, 1536]: q|k|v
__device__ float g_bias[HEADS * SEQ * SEQ];  // [h][l][m] expanded rel-pos bias
__device__ float g_attnout[MROWS * DIM];     // [B,L,C] attention output
__device__ float g_xres[MROWS * DIM];        // x + proj(attn)
__device__ float g_mlp1[MROWS * MLPH];       // gelu(fc1)

// ---------------- helpers ----------------------------------------------------
__device__ __forceinline__ float to_tf32(float x) {
    uint32_t u;
    asm("cvt.rna.tf32.f32 %0, %1;" : "=r"(u) : "f"(x));
    return __uint_as_float(u);
}

__device__ __forceinline__ void mma_tf32(float* c, const uint32_t* a,
                                         uint32_t b0, uint32_t b1) {
    asm volatile(
        "mma.sync.aligned.m16n8k8.row.col.f32.tf32.tf32.f32 "
        "{%0,%1,%2,%3}, {%4,%5,%6,%7}, {%8,%9}, {%0,%1,%2,%3};"
        : "+f"(c[0]), "+f"(c[1]), "+f"(c[2]), "+f"(c[3])
        : "r"(a[0]), "r"(a[1]), "r"(a[2]), "r"(a[3]), "r"(b0), "r"(b1));
}

// ---------------- LayerNorm: one block per row of 512 ----------------------
__global__ void __launch_bounds__(128) ln_kernel(const float* __restrict__ x,
                                                 const float* __restrict__ g,
                                                 const float* __restrict__ b,
                                                 float* __restrict__ out)
{
    const int row = blockIdx.x;
    const int t = threadIdx.x;
    const float4 v = ((const float4*)(x + (size_t)row * DIM))[t];
    float s  = v.x + v.y + v.z + v.w;
    float s2 = v.x*v.x + v.y*v.y + v.z*v.z + v.w*v.w;
    #pragma unroll
    for (int o = 16; o > 0; o >>= 1) {
        s  += __shfl_xor_sync(0xffffffffu, s,  o);
        s2 += __shfl_xor_sync(0xffffffffu, s2, o);
    }
    __shared__ float rs[4], rs2[4];
    if ((t & 31) == 0) { rs[t >> 5] = s; rs2[t >> 5] = s2; }
    __syncthreads();
    s  = rs[0] + rs[1] + rs[2] + rs[3];
    s2 = rs2[0] + rs2[1] + rs2[2] + rs2[3];
    const float mean = s * (1.0f / DIM);
    const float var  = s2 * (1.0f / DIM) - mean * mean;
    const float inv  = rsqrtf(var + 1e-5f);
    const float4 gg = ((const float4*)g)[t];
    const float4 bb = ((const float4*)b)[t];
    float4 o4;
    o4.x = (v.x - mean) * inv * gg.x + bb.x;
    o4.y = (v.y - mean) * inv * gg.y + bb.y;
    o4.z = (v.z - mean) * inv * gg.z + bb.z;
    o4.w = (v.w - mean) * inv * gg.w + bb.w;
    ((float4*)(out + (size_t)row * DIM))[t] = o4;
}

// ---------------- bias expand: g_bias[h][l][m] = table[rel[l][m]*16+h] ------
__global__ void __launch_bounds__(256) bias_expand_kernel(const int* __restrict__ rel,
                                                          const float* __restrict__ table)
{
    const unsigned idx = blockIdx.x * 256u + threadIdx.x;   // < 16*1024*1024
    const int m = idx & 1023;
    const int l = (idx >> 10) & 1023;
    const int h = idx >> 20;
    const int ri = rel[l * SEQ + m];
    g_bias[idx] = table[ri * HEADS + h];
}

// ---------------- tf32 tensor-core GEMM ------------------------------------
enum { EPI_BIAS = 0, EPI_GELU = 1, EPI_RES = 2 };

template <int EPI>
__global__ void __launch_bounds__(256) gemm_tc(const float* __restrict__ A,
                                               const float* __restrict__ W,
                                               const float* __restrict__ bias,
                                               const float* __restrict__ R,
                                               float* __restrict__ C,
                                               int M, int N, int K)
{
    __shared__ float As[128][36];
    __shared__ float Bs[32][136];

    const int bm = blockIdx.y * 128, bn = blockIdx.x * 128;
    const int tid = threadIdx.x;
    const int warp = tid >> 5, lane = tid & 31;
    const int wm = (warp & 3) * 32, wn = (warp >> 2) * 64;
    const int g = lane >> 2, t4 = lane & 3;

    float4 pa[4], pb[4];
    #pragma unroll
    for (int i = 0; i < 4; i++) {
        const int ia = tid + i * 256;
        pa[i] = *(const float4*)(A + (size_t)(bm + (ia >> 3)) * K + (ia & 7) * 4);
        const int ib = tid + i * 256;
        pb[i] = *(const float4*)(W + (size_t)(ib >> 5) * N + bn + (ib & 31) * 4);
    }

    float acc[2][8][4];
    #pragma unroll
    for (int mi = 0; mi < 2; mi++)
        #pragma unroll
        for (int ni = 0; ni < 8; ni++)
            #pragma unroll
            for (int c = 0; c < 4; c++) acc[mi][ni][c] = 0.0f;

    const int nk = K >> 5;
    for (int kt = 0; kt < nk; kt++) {
        #pragma unroll
        for (int i = 0; i < 4; i++) {
            const int ia = tid + i * 256;
            float4 va = pa[i];
            va.x = to_tf32(va.x); va.y = to_tf32(va.y);
            va.z = to_tf32(va.z); va.w = to_tf32(va.w);
            *(float4*)&As[ia >> 3][(ia & 7) * 4] = va;
            const int ib = tid + i * 256;
            float4 vb = pb[i];
            vb.x = to_tf32(vb.x); vb.y = to_tf32(vb.y);
            vb.z = to_tf32(vb.z); vb.w = to_tf32(vb.w);
            *(float4*)&Bs[ib >> 5][(ib & 31) * 4] = vb;
        }
        __syncthreads();
        if (kt + 1 < nk) {
            const int k0 = (kt + 1) * 32;
            #pragma unroll
            for (int i = 0; i < 4; i++) {
                const int ia = tid + i * 256;
                pa[i] = *(const float4*)(A + (size_t)(bm + (ia >> 3)) * K + k0 + (ia & 7) * 4);
                const int ib = tid + i * 256;
                pb[i] = *(const float4*)(W + (size_t)(k0 + (ib >> 5)) * N + bn + (ib & 31) * 4);
            }
        }
        #pragma unroll
        for (int ks = 0; ks < 4; ks++) {
            const int kk = ks * 8;
            uint32_t af[2][4];
            #pragma unroll
            for (int mi = 0; mi < 2; mi++) {
                const int rm = wm + mi * 16;
                af[mi][0] = __float_as_uint(As[rm + g][kk + t4]);
                af[mi][1] = __float_as_uint(As[rm + g + 8][kk + t4]);
                af[mi][2] = __float_as_uint(As[rm + g][kk + t4 + 4]);
                af[mi][3] = __float_as_uint(As[rm + g + 8][kk + t4 + 4]);
            }
            #pragma unroll
            for (int ni = 0; ni < 8; ni++) {
                const int cn = wn + ni * 8 + g;
                const uint32_t b0 = __float_as_uint(Bs[kk + t4][cn]);
                const uint32_t b1 = __float_as_uint(Bs[kk + t4 + 4][cn]);
                mma_tf32(acc[0][ni], af[0], b0, b1);
                mma_tf32(acc[1][ni], af[1], b0, b1);
            }
        }
        __syncthreads();
    }

    #pragma unroll
    for (int mi = 0; mi < 2; mi++) {
        const int r0 = bm + wm + mi * 16 + g;
        #pragma unroll
        for (int ni = 0; ni < 8; ni++) {
            const int col = bn + wn + ni * 8 + t4 * 2;
            const float b0 = bias[col], b1 = bias[col + 1];
            float v[4];
            v[0] = acc[mi][ni][0] + b0;
            v[1] = acc[mi][ni][1] + b1;
            v[2] = acc[mi][ni][2] + b0;
            v[3] = acc[mi][ni][3] + b1;
            if (EPI == EPI_GELU) {
                #pragma unroll
                for (int c = 0; c < 4; c++)
                    v[c] = 0.5f * v[c] * (1.0f + erff(v[c] * 0.70710678118654752f));
            }
            const size_t off0 = (size_t)r0 * N + col;
            const size_t off1 = (size_t)(r0 + 8) * N + col;
            float2 o0 = make_float2(v[0], v[1]);
            float2 o1 = make_float2(v[2], v[3]);
            if (EPI == EPI_RES) {
                const float2 r4a = *(const float2*)(R + off0);
                const float2 r4b = *(const float2*)(R + off1);
                o0.x += r4a.x; o0.y += r4a.y;
                o1.x += r4b.x; o1.y += r4b.y;
            }
            *(float2*)(C + off0) = o0;
            *(float2*)(C + off1) = o1;
        }
    }
}

// ---------------- Flash attention on tensor cores ---------------------------
// Block: 64 queries x one (b,h); 4 warps, 16 query rows each; 64-key tiles.
// QK^T and PV both via m16n8k8 tf32. Online softmax in registers.
__global__ void __launch_bounds__(128) attn_tc_kernel(float* __restrict__ out)
{
    __shared__ float Ks[64][36];      // [key][d]  (B-operand of QK^T)
    __shared__ float Vs[64][36];      // [key][d]  (B-operand of PV)
    __shared__ float Ps[4][16][68];   // warp-private P tile (A-operand of PV)

    const int b = blockIdx.z, h = blockIdx.y, q0 = blockIdx.x * 64;
    const int tid = threadIdx.x;
    const int warp = tid >> 5, lane = tid & 31;
    const int g = lane >> 2, t4 = lane & 3;
    const int wq = warp * 16;                 // warp's query-row offset in tile

    const float scale = 0.17677669529663687f; // 1/sqrt(32)

    // ---- Q fragments (held for whole kernel), scaled + tf32 ----
    uint32_t qf[4][4];                        // [ks][frag]
    {
        const float* q0p = g_qkv + ((size_t)(b * SEQ + q0 + wq + g)) * (3 * DIM) + h * HD;
        const float* q1p = q0p + 8 * (3 * DIM);
        #pragma unroll
        for (int ks = 0; ks < 4; ks++) {
            const int kk = ks * 8;
            qf[ks][0] = __float_as_uint(to_tf32(q0p[kk + t4] * scale));
            qf[ks][1] = __float_as_uint(to_tf32(q1p[kk + t4] * scale));
            qf[ks][2] = __float_as_uint(to_tf32(q0p[kk + t4 + 4] * scale));
            qf[ks][3] = __float_as_uint(to_tf32(q1p[kk + t4 + 4] * scale));
        }
    }

    float m0 = -1e30f, m1 = -1e30f, li0 = 0.0f, li1 = 0.0f;
    float acc_o[4][4];
    #pragma unroll
    for (int ni = 0; ni < 4; ni++)
        #pragma unroll
        for (int c = 0; c < 4; c++) acc_o[ni][c] = 0.0f;

    const float* bias0 = g_bias + ((size_t)h * SEQ + q0 + wq + g) * SEQ;
    const float* bias1 = bias0 + 8 * SEQ;

    for (int k0 = 0; k0 < SEQ; k0 += 64) {
        __syncthreads();
        // ---- stage K,V tile (tf32) ----
        #pragma unroll
        for (int i = 0; i < 4; i++) {
            const int fid = tid + i * 128;
            const int key = fid >> 3, c4 = (fid & 7) * 4;
            const float* kp = g_qkv + ((size_t)(b * SEQ + k0 + key)) * (3 * DIM)
                              + DIM + h * HD + c4;
            const float4 kv = *(const float4*)kp;
            const float4 vv = *(const float4*)(kp + DIM);
            Ks[key][c4 + 0] = to_tf32(kv.x);
            Ks[key][c4 + 1] = to_tf32(kv.y);
            Ks[key][c4 + 2] = to_tf32(kv.z);
            Ks[key][c4 + 3] = to_tf32(kv.w);
            Vs[key][c4 + 0] = to_tf32(vv.x);
            Vs[key][c4 + 1] = to_tf32(vv.y);
            Vs[key][c4 + 2] = to_tf32(vv.z);
            Vs[key][c4 + 3] = to_tf32(vv.w);
        }
        __syncthreads();

        // ---- S = Q @ K^T  (M=16, N=64, K=32 per warp) ----
        float sacc[8][4];
        #pragma unroll
        for (int ni = 0; ni < 8; ni++)
            #pragma unroll
            for (int c = 0; c < 4; c++) sacc[ni][c] = 0.0f;
        #pragma unroll
        for (int ks = 0; ks < 4; ks++) {
            const int kk = ks * 8;
            #pragma unroll
            for (int ni = 0; ni < 8; ni++) {
                const uint32_t b0 = __float_as_uint(Ks[ni * 8 + g][kk + t4]);
                const uint32_t b1 = __float_as_uint(Ks[ni * 8 + g][kk + t4 + 4]);
                mma_tf32(sacc[ni], qf[ks], b0, b1);
            }
        }
        // ---- + bias (direct gmem, matches C layout) ----
        #pragma unroll
        for (int ni = 0; ni < 8; ni++) {
            const int col = k0 + ni * 8 + t4 * 2;
            const float2 bv0 = *(const float2*)(bias0 + col);
            const float2 bv1 = *(const float2*)(bias1 + col);
            sacc[ni][0] += bv0.x; sacc[ni][1] += bv0.y;
            sacc[ni][2] += bv1.x; sacc[ni][3] += bv1.y;
        }

        // ---- online softmax ----
        float vmax0 = -1e30f, vmax1 = -1e30f;
        #pragma unroll
        for (int ni = 0; ni < 8; ni++) {
            vmax0 = fmaxf(vmax0, fmaxf(sacc[ni][0], sacc[ni][1]));
            vmax1 = fmaxf(vmax1, fmaxf(sacc[ni][2], sacc[ni][3]));
        }
        #pragma unroll
        for (int o = 1; o <= 2; o <<= 1) {
            vmax0 = fmaxf(vmax0, __shfl_xor_sync(0xffffffffu, vmax0, o));
            vmax1 = fmaxf(vmax1, __shfl_xor_sync(0xffffffffu, vmax1, o));
        }
        const float nm0 = fmaxf(m0, vmax0);
        const float nm1 = fmaxf(m1, vmax1);
        const float corr0 = __expf(m0 - nm0);
        const float corr1 = __expf(m1 - nm1);
        m0 = nm0; m1 = nm1;
        float rs0 = 0.0f, rs1 = 0.0f;

        __syncwarp();
        #pragma unroll
        for (int ni = 0; ni < 8; ni++) {
            const float p0 = __expf(sacc[ni][0] - m0);
            const float p1 = __expf(sacc[ni][1] - m0);
            const float p2 = __expf(sacc[ni][2] - m1);
            const float p3 = __expf(sacc[ni][3] - m1);
            rs0 += p0 + p1; rs1 += p2 + p3;
            const int col = ni * 8 + t4 * 2;
            Ps[warp][g][col]         = to_tf32(p0);
            Ps[warp][g][col + 1]     = to_tf32(p1);
            Ps[warp][g + 8][col]     = to_tf32(p2);
            Ps[warp][g + 8][col + 1] = to_tf32(p3);
        }
        li0 = li0 * corr0 + rs0;
        li1 = li1 * corr1 + rs1;
        #pragma unroll
        for (int ni = 0; ni < 4; ni++) {
            acc_o[ni][0] *= corr0; acc_o[ni][1] *= corr0;
            acc_o[ni][2] *= corr1; acc_o[ni][3] *= corr1;
        }
        __syncwarp();

        // ---- O += P @ V  (M=16, N=32, K=64 per warp) ----
        #pragma unroll
        for (int ks = 0; ks < 8; ks++) {
            const int kk = ks * 8;
            uint32_t af[4];
            af[0] = __float_as_uint(Ps[warp][g][kk + t4]);
            af[1] = __float_as_uint(Ps[warp][g + 8][kk + t4]);
            af[2] = __float_as_uint(Ps[warp][g][kk + t4 + 4]);
            af[3] = __float_as_uint(Ps[warp][g + 8][kk + t4 + 4]);
            #pragma unroll
            for (int ni = 0; ni < 4; ni++) {
                const uint32_t b0 = __float_as_uint(Vs[kk + t4][ni * 8 + g]);
                const uint32_t b1 = __float_as_uint(Vs[kk + t4 + 4][ni * 8 + g]);
                mma_tf32(acc_o[ni], af, b0, b1);
            }
        }
    }

    // ---- finalize: sum li across t4 lanes, divide, store ----
    #pragma unroll
    for (int o = 1; o <= 2; o <<= 1) {
        li0 += __shfl_xor_sync(0xffffffffu, li0, o);
        li1 += __shfl_xor_sync(0xffffffffu, li1, o);
    }
    const float inv0 = 1.0f / li0;
    const float inv1 = 1.0f / li1;
    float* o0p = out + ((size_t)(b * SEQ + q0 + wq + g)) * DIM + h * HD;
    float* o1p = o0p + 8 * DIM;
    #pragma unroll
    for (int ni = 0; ni < 4; ni++) {
        const int col = ni * 8 + t4 * 2;
        *(float2*)(o0p + col) = make_float2(acc_o[ni][0] * inv0, acc_o[ni][1] * inv0);
        *(float2*)(o1p + col) = make_float2(acc_o[ni][2] * inv1, acc_o[ni][3] * inv1);
    }
}

// ---------------- launch -----------------------------------------------------
extern "C" void kernel_launch(void* const* d_in, const int* in_sizes, int n_in,
                              void* d_out, int out_size)
{
    const float* x      = (const float*)d_in[0];
    const int*   rel    = (const int*)  d_in[1];
    const float* table  = (const float*)d_in[2];
    const float* qkv_w  = (const float*)d_in[3];
    const float* qkv_b  = (const float*)d_in[4];
    const float* proj_w = (const float*)d_in[5];
    const float* proj_b = (const float*)d_in[6];
    const float* n1_g   = (const float*)d_in[7];
    const float* n1_b   = (const float*)d_in[8];
    const float* n2_g   = (const float*)d_in[9];
    const float* n2_b   = (const float*)d_in[10];
    const float* fc1_w  = (const float*)d_in[11];
    const float* fc1_b  = (const float*)d_in[12];
    const float* fc2_w  = (const float*)d_in[13];
    const float* fc2_b  = (const float*)d_in[14];
    float* out = (float*)d_out;

    float *h, *qkv, *attnout, *xres, *mlp1;
    cudaGetSymbolAddress((void**)&h,       g_h);
    cudaGetSymbolAddress((void**)&qkv,     g_qkv);
    cudaGetSymbolAddress((void**)&attnout, g_attnout);
    cudaGetSymbolAddress((void**)&xres,    g_xres);
    cudaGetSymbolAddress((void**)&mlp1,    g_mlp1);

    // 1. h = LN1(x)
    ln_kernel<<<MROWS, 128>>>(x, n1_g, n1_b, h);
    // 2. qkv = h @ qkv_w + qkv_b        [8192, 1536]
    gemm_tc<EPI_BIAS><<<dim3(12, 64), 256>>>(h, qkv_w, qkv_b, nullptr, qkv,
                                             MROWS, 3 * DIM, DIM);
    // 3. expand rel-pos bias to [H, L, L]
    bias_expand_kernel<<<(HEADS * SEQ * SEQ) / 256, 256>>>(rel, table);
    // 4. flash attention (tensor cores) -> [B, L, C]
    attn_tc_kernel<<<dim3(16, HEADS, BATCH), 128>>>(attnout);
    // 5. xres = x + attnout @ proj_w + proj_b
    gemm_tc<EPI_RES><<<dim3(4, 64), 256>>>(attnout, proj_w, proj_b, x, xres,
                                           MROWS, DIM, DIM);
    // 6. h = LN2(xres)
    ln_kernel<<<MROWS, 128>>>(xres, n2_g, n2_b, h);
    // 7. mlp1 = gelu(h @ fc1_w + fc1_b)  [8192, 2048]
    gemm_tc<EPI_GELU><<<dim3(16, 64), 256>>>(h, fc1_w, fc1_b, nullptr, mlp1,
                                             MROWS, MLPH, DIM);
    // 8. out = xres + mlp1 @ fc2_w + fc2_b
    gemm_tc<EPI_RES><<<dim3(4, 64), 256>>>(mlp1, fc2_w, fc2_b, xres, out,
                                           MROWS, DIM, MLPH);
}

// round 5
// speedup vs baseline: 2.7038x; 1.1704x over previous
#include <cuda_runtime.h>
#include <math.h>
#include <stdint.h>

#define BATCH 8
#define SEQ 1024
#define DIM 512
#define HEADS 16
#define HD 32
#define MROWS (BATCH*SEQ)   /* 8192 */
#define MLPH 2048

// ---------------- scratch (device globals; no allocations allowed) ----------
__device__ float g_h[MROWS * DIM];           // LN1 out, reused for LN2 out
__device__ float g_qkv[MROWS * 3 * DIM];     // [row, 1536]: q|k|v
__device__ float g_bias[HEADS * SEQ * SEQ];  // [h][l][m] expanded rel-pos bias
__device__ float g_attnout[MROWS * DIM];     // [B,L,C] attention output
__device__ float g_xres[MROWS * DIM];        // x + proj(attn)
__device__ float g_mlp1[MROWS * MLPH];       // gelu(fc1)

// ---------------- helpers ----------------------------------------------------
__device__ __forceinline__ float to_tf32(float x) {
    uint32_t u;
    asm("cvt.rna.tf32.f32 %0, %1;" : "=r"(u) : "f"(x));
    return __uint_as_float(u);
}

__device__ __forceinline__ void mma_tf32(float* c, const uint32_t* a,
                                         uint32_t b0, uint32_t b1) {
    asm volatile(
        "mma.sync.aligned.m16n8k8.row.col.f32.tf32.tf32.f32 "
        "{%0,%1,%2,%3}, {%4,%5,%6,%7}, {%8,%9}, {%0,%1,%2,%3};"
        : "+f"(c[0]), "+f"(c[1]), "+f"(c[2]), "+f"(c[3])
        : "r"(a[0]), "r"(a[1]), "r"(a[2]), "r"(a[3]), "r"(b0), "r"(b1));
}

// ---------------- LayerNorm: one block per row of 512 ----------------------
__global__ void __launch_bounds__(128) ln_kernel(const float* __restrict__ x,
                                                 const float* __restrict__ g,
                                                 const float* __restrict__ b,
                                                 float* __restrict__ out)
{
    const int row = blockIdx.x;
    const int t = threadIdx.x;
    const float4 v = ((const float4*)(x + (size_t)row * DIM))[t];
    float s  = v.x + v.y + v.z + v.w;
    float s2 = v.x*v.x + v.y*v.y + v.z*v.z + v.w*v.w;
    #pragma unroll
    for (int o = 16; o > 0; o >>= 1) {
        s  += __shfl_xor_sync(0xffffffffu, s,  o);
        s2 += __shfl_xor_sync(0xffffffffu, s2, o);
    }
    __shared__ float rs[4], rs2[4];
    if ((t & 31) == 0) { rs[t >> 5] = s; rs2[t >> 5] = s2; }
    __syncthreads();
    s  = rs[0] + rs[1] + rs[2] + rs[3];
    s2 = rs2[0] + rs2[1] + rs2[2] + rs2[3];
    const float mean = s * (1.0f / DIM);
    const float var  = s2 * (1.0f / DIM) - mean * mean;
    const float inv  = rsqrtf(var + 1e-5f);
    const float4 gg = ((const float4*)g)[t];
    const float4 bb = ((const float4*)b)[t];
    float4 o4;
    o4.x = (v.x - mean) * inv * gg.x + bb.x;
    o4.y = (v.y - mean) * inv * gg.y + bb.y;
    o4.z = (v.z - mean) * inv * gg.z + bb.z;
    o4.w = (v.w - mean) * inv * gg.w + bb.w;
    ((float4*)(out + (size_t)row * DIM))[t] = o4;
}

// ---------------- bias expand: g_bias[h][l][m] = table[rel[l][m]*16+h] ------
__global__ void __launch_bounds__(256) bias_expand_kernel(const int* __restrict__ rel,
                                                          const float* __restrict__ table)
{
    const unsigned idx = blockIdx.x * 256u + threadIdx.x;   // < 16*1024*1024
    const int m = idx & 1023;
    const int l = (idx >> 10) & 1023;
    const int h = idx >> 20;
    const int ri = rel[l * SEQ + m];
    g_bias[idx] = table[ri * HEADS + h];
}

// ---------------- tf32 tensor-core GEMM ------------------------------------
enum { EPI_BIAS = 0, EPI_GELU = 1, EPI_RES = 2 };

template <int EPI>
__global__ void __launch_bounds__(256) gemm_tc(const float* __restrict__ A,
                                               const float* __restrict__ W,
                                               const float* __restrict__ bias,
                                               const float* __restrict__ R,
                                               float* __restrict__ C,
                                               int M, int N, int K)
{
    __shared__ float As[128][36];
    __shared__ float Bs[32][136];

    const int bm = blockIdx.y * 128, bn = blockIdx.x * 128;
    const int tid = threadIdx.x;
    const int warp = tid >> 5, lane = tid & 31;
    const int wm = (warp & 3) * 32, wn = (warp >> 2) * 64;
    const int g = lane >> 2, t4 = lane & 3;

    float4 pa[4], pb[4];
    #pragma unroll
    for (int i = 0; i < 4; i++) {
        const int ia = tid + i * 256;
        pa[i] = *(const float4*)(A + (size_t)(bm + (ia >> 3)) * K + (ia & 7) * 4);
        const int ib = tid + i * 256;
        pb[i] = *(const float4*)(W + (size_t)(ib >> 5) * N + bn + (ib & 31) * 4);
    }

    float acc[2][8][4];
    #pragma unroll
    for (int mi = 0; mi < 2; mi++)
        #pragma unroll
        for (int ni = 0; ni < 8; ni++)
            #pragma unroll
            for (int c = 0; c < 4; c++) acc[mi][ni][c] = 0.0f;

    const int nk = K >> 5;
    for (int kt = 0; kt < nk; kt++) {
        #pragma unroll
        for (int i = 0; i < 4; i++) {
            const int ia = tid + i * 256;
            float4 va = pa[i];
            va.x = to_tf32(va.x); va.y = to_tf32(va.y);
            va.z = to_tf32(va.z); va.w = to_tf32(va.w);
            *(float4*)&As[ia >> 3][(ia & 7) * 4] = va;
            const int ib = tid + i * 256;
            float4 vb = pb[i];
            vb.x = to_tf32(vb.x); vb.y = to_tf32(vb.y);
            vb.z = to_tf32(vb.z); vb.w = to_tf32(vb.w);
            *(float4*)&Bs[ib >> 5][(ib & 31) * 4] = vb;
        }
        __syncthreads();
        if (kt + 1 < nk) {
            const int k0 = (kt + 1) * 32;
            #pragma unroll
            for (int i = 0; i < 4; i++) {
                const int ia = tid + i * 256;
                pa[i] = *(const float4*)(A + (size_t)(bm + (ia >> 3)) * K + k0 + (ia & 7) * 4);
                const int ib = tid + i * 256;
                pb[i] = *(const float4*)(W + (size_t)(k0 + (ib >> 5)) * N + bn + (ib & 31) * 4);
            }
        }
        #pragma unroll
        for (int ks = 0; ks < 4; ks++) {
            const int kk = ks * 8;
            uint32_t af[2][4];
            #pragma unroll
            for (int mi = 0; mi < 2; mi++) {
                const int rm = wm + mi * 16;
                af[mi][0] = __float_as_uint(As[rm + g][kk + t4]);
                af[mi][1] = __float_as_uint(As[rm + g + 8][kk + t4]);
                af[mi][2] = __float_as_uint(As[rm + g][kk + t4 + 4]);
                af[mi][3] = __float_as_uint(As[rm + g + 8][kk + t4 + 4]);
            }
            #pragma unroll
            for (int ni = 0; ni < 8; ni++) {
                const int cn = wn + ni * 8 + g;
                const uint32_t b0 = __float_as_uint(Bs[kk + t4][cn]);
                const uint32_t b1 = __float_as_uint(Bs[kk + t4 + 4][cn]);
                mma_tf32(acc[0][ni], af[0], b0, b1);
                mma_tf32(acc[1][ni], af[1], b0, b1);
            }
        }
        __syncthreads();
    }

    #pragma unroll
    for (int mi = 0; mi < 2; mi++) {
        const int r0 = bm + wm + mi * 16 + g;
        #pragma unroll
        for (int ni = 0; ni < 8; ni++) {
            const int col = bn + wn + ni * 8 + t4 * 2;
            const float b0 = bias[col], b1 = bias[col + 1];
            float v[4];
            v[0] = acc[mi][ni][0] + b0;
            v[1] = acc[mi][ni][1] + b1;
            v[2] = acc[mi][ni][2] + b0;
            v[3] = acc[mi][ni][3] + b1;
            if (EPI == EPI_GELU) {
                #pragma unroll
                for (int c = 0; c < 4; c++)
                    v[c] = 0.5f * v[c] * (1.0f + erff(v[c] * 0.70710678118654752f));
            }
            const size_t off0 = (size_t)r0 * N + col;
            const size_t off1 = (size_t)(r0 + 8) * N + col;
            float2 o0 = make_float2(v[0], v[1]);
            float2 o1 = make_float2(v[2], v[3]);
            if (EPI == EPI_RES) {
                const float2 r4a = *(const float2*)(R + off0);
                const float2 r4b = *(const float2*)(R + off1);
                o0.x += r4a.x; o0.y += r4a.y;
                o1.x += r4b.x; o1.y += r4b.y;
            }
            *(float2*)(C + off0) = o0;
            *(float2*)(C + off1) = o1;
        }
    }
}

// ---------------- Flash attention on tensor cores ---------------------------
// Block: 128 queries x one (b,h); 8 warps, 16 query rows each; 64-key tiles
// shared by all warps. K/V register-prefetch double buffering.
__global__ void __launch_bounds__(256) attn_tc_kernel(float* __restrict__ out)
{
    __shared__ float Ks[64][36];      // [key][d]  (B-operand of QK^T)
    __shared__ float Vs[64][36];      // [key][d]  (B-operand of PV)
    __shared__ float Ps[8][16][68];   // warp-private P tile (A-operand of PV)

    const int b = blockIdx.z, h = blockIdx.y, q0 = blockIdx.x * 128;
    const int tid = threadIdx.x;
    const int warp = tid >> 5, lane = tid & 31;
    const int g = lane >> 2, t4 = lane & 3;
    const int wq = warp * 16;

    const float scale = 0.17677669529663687f; // 1/sqrt(32)

    // ---- Q fragments (held for whole kernel), scaled + tf32 ----
    uint32_t qf[4][4];
    {
        const float* q0p = g_qkv + ((size_t)(b * SEQ + q0 + wq + g)) * (3 * DIM) + h * HD;
        const float* q1p = q0p + 8 * (3 * DIM);
        #pragma unroll
        for (int ks = 0; ks < 4; ks++) {
            const int kk = ks * 8;
            qf[ks][0] = __float_as_uint(to_tf32(q0p[kk + t4] * scale));
            qf[ks][1] = __float_as_uint(to_tf32(q1p[kk + t4] * scale));
            qf[ks][2] = __float_as_uint(to_tf32(q0p[kk + t4 + 4] * scale));
            qf[ks][3] = __float_as_uint(to_tf32(q1p[kk + t4 + 4] * scale));
        }
    }

    float m0 = -1e30f, m1 = -1e30f, li0 = 0.0f, li1 = 0.0f;
    float acc_o[4][4];
    #pragma unroll
    for (int ni = 0; ni < 4; ni++)
        #pragma unroll
        for (int c = 0; c < 4; c++) acc_o[ni][c] = 0.0f;

    const float* bias0 = g_bias + ((size_t)h * SEQ + q0 + wq + g) * SEQ;
    const float* bias1 = bias0 + 8 * SEQ;

    // staging map: fid = tid + i*256 -> key = fid>>3, c4 = (fid&7)*4
    float4 kpre[2], vpre[2];
    #pragma unroll
    for (int i = 0; i < 2; i++) {
        const int fid = tid + i * 256;
        const float* kp = g_qkv + ((size_t)(b * SEQ + (fid >> 3))) * (3 * DIM)
                          + DIM + h * HD + (fid & 7) * 4;
        kpre[i] = *(const float4*)kp;
        vpre[i] = *(const float4*)(kp + DIM);
    }

    for (int k0 = 0; k0 < SEQ; k0 += 64) {
        __syncthreads();   // previous tile fully consumed
        #pragma unroll
        for (int i = 0; i < 2; i++) {
            const int fid = tid + i * 256;
            const int key = fid >> 3, c4 = (fid & 7) * 4;
            float4 kv = kpre[i], vv = vpre[i];
            kv.x = to_tf32(kv.x); kv.y = to_tf32(kv.y);
            kv.z = to_tf32(kv.z); kv.w = to_tf32(kv.w);
            vv.x = to_tf32(vv.x); vv.y = to_tf32(vv.y);
            vv.z = to_tf32(vv.z); vv.w = to_tf32(vv.w);
            *(float4*)&Ks[key][c4] = kv;
            *(float4*)&Vs[key][c4] = vv;
        }
        __syncthreads();
        if (k0 + 64 < SEQ) {
            #pragma unroll
            for (int i = 0; i < 2; i++) {
                const int fid = tid + i * 256;
                const float* kp = g_qkv + ((size_t)(b * SEQ + k0 + 64 + (fid >> 3))) * (3 * DIM)
                                  + DIM + h * HD + (fid & 7) * 4;
                kpre[i] = *(const float4*)kp;
                vpre[i] = *(const float4*)(kp + DIM);
            }
        }

        // ---- S = Q @ K^T  (M=16, N=64, K=32 per warp) ----
        float sacc[8][4];
        #pragma unroll
        for (int ni = 0; ni < 8; ni++)
            #pragma unroll
            for (int c = 0; c < 4; c++) sacc[ni][c] = 0.0f;
        #pragma unroll
        for (int ks = 0; ks < 4; ks++) {
            const int kk = ks * 8;
            #pragma unroll
            for (int ni = 0; ni < 8; ni++) {
                const uint32_t b0 = __float_as_uint(Ks[ni * 8 + g][kk + t4]);
                const uint32_t b1 = __float_as_uint(Ks[ni * 8 + g][kk + t4 + 4]);
                mma_tf32(sacc[ni], qf[ks], b0, b1);
            }
        }
        // ---- + bias (direct gmem, L2-resident) ----
        #pragma unroll
        for (int ni = 0; ni < 8; ni++) {
            const int col = k0 + ni * 8 + t4 * 2;
            const float2 bv0 = *(const float2*)(bias0 + col);
            const float2 bv1 = *(const float2*)(bias1 + col);
            sacc[ni][0] += bv0.x; sacc[ni][1] += bv0.y;
            sacc[ni][2] += bv1.x; sacc[ni][3] += bv1.y;
        }

        // ---- online softmax ----
        float vmax0 = -1e30f, vmax1 = -1e30f;
        #pragma unroll
        for (int ni = 0; ni < 8; ni++) {
            vmax0 = fmaxf(vmax0, fmaxf(sacc[ni][0], sacc[ni][1]));
            vmax1 = fmaxf(vmax1, fmaxf(sacc[ni][2], sacc[ni][3]));
        }
        #pragma unroll
        for (int o = 1; o <= 2; o <<= 1) {
            vmax0 = fmaxf(vmax0, __shfl_xor_sync(0xffffffffu, vmax0, o));
            vmax1 = fmaxf(vmax1, __shfl_xor_sync(0xffffffffu, vmax1, o));
        }
        const float nm0 = fmaxf(m0, vmax0);
        const float nm1 = fmaxf(m1, vmax1);
        const float corr0 = __expf(m0 - nm0);
        const float corr1 = __expf(m1 - nm1);
        m0 = nm0; m1 = nm1;
        float rs0 = 0.0f, rs1 = 0.0f;

        __syncwarp();
        #pragma unroll
        for (int ni = 0; ni < 8; ni++) {
            const float p0 = __expf(sacc[ni][0] - m0);
            const float p1 = __expf(sacc[ni][1] - m0);
            const float p2 = __expf(sacc[ni][2] - m1);
            const float p3 = __expf(sacc[ni][3] - m1);
            rs0 += p0 + p1; rs1 += p2 + p3;
            const int col = ni * 8 + t4 * 2;
            *(float2*)&Ps[warp][g][col]     = make_float2(to_tf32(p0), to_tf32(p1));
            *(float2*)&Ps[warp][g + 8][col] = make_float2(to_tf32(p2), to_tf32(p3));
        }
        li0 = li0 * corr0 + rs0;
        li1 = li1 * corr1 + rs1;
        #pragma unroll
        for (int ni = 0; ni < 4; ni++) {
            acc_o[ni][0] *= corr0; acc_o[ni][1] *= corr0;
            acc_o[ni][2] *= corr1; acc_o[ni][3] *= corr1;
        }
        __syncwarp();

        // ---- O += P @ V  (M=16, N=32, K=64 per warp) ----
        #pragma unroll
        for (int ks = 0; ks < 8; ks++) {
            const int kk = ks * 8;
            uint32_t af[4];
            af[0] = __float_as_uint(Ps[warp][g][kk + t4]);
            af[1] = __float_as_uint(Ps[warp][g + 8][kk + t4]);
            af[2] = __float_as_uint(Ps[warp][g][kk + t4 + 4]);
            af[3] = __float_as_uint(Ps[warp][g + 8][kk + t4 + 4]);
            #pragma unroll
            for (int ni = 0; ni < 4; ni++) {
                const uint32_t b0 = __float_as_uint(Vs[kk + t4][ni * 8 + g]);
                const uint32_t b1 = __float_as_uint(Vs[kk + t4 + 4][ni * 8 + g]);
                mma_tf32(acc_o[ni], af, b0, b1);
            }
        }
    }

    // ---- finalize ----
    #pragma unroll
    for (int o = 1; o <= 2; o <<= 1) {
        li0 += __shfl_xor_sync(0xffffffffu, li0, o);
        li1 += __shfl_xor_sync(0xffffffffu, li1, o);
    }
    const float inv0 = 1.0f / li0;
    const float inv1 = 1.0f / li1;
    float* o0p = out + ((size_t)(b * SEQ + q0 + wq + g)) * DIM + h * HD;
    float* o1p = o0p + 8 * DIM;
    #pragma unroll
    for (int ni = 0; ni < 4; ni++) {
        const int col = ni * 8 + t4 * 2;
        *(float2*)(o0p + col) = make_float2(acc_o[ni][0] * inv0, acc_o[ni][1] * inv0);
        *(float2*)(o1p + col) = make_float2(acc_o[ni][2] * inv1, acc_o[ni][3] * inv1);
    }
}

// ---------------- launch -----------------------------------------------------
extern "C" void kernel_launch(void* const* d_in, const int* in_sizes, int n_in,
                              void* d_out, int out_size)
{
    const float* x      = (const float*)d_in[0];
    const int*   rel    = (const int*)  d_in[1];
    const float* table  = (const float*)d_in[2];
    const float* qkv_w  = (const float*)d_in[3];
    const float* qkv_b  = (const float*)d_in[4];
    const float* proj_w = (const float*)d_in[5];
    const float* proj_b = (const float*)d_in[6];
    const float* n1_g   = (const float*)d_in[7];
    const float* n1_b   = (const float*)d_in[8];
    const float* n2_g   = (const float*)d_in[9];
    const float* n2_b   = (const float*)d_in[10];
    const float* fc1_w  = (const float*)d_in[11];
    const float* fc1_b  = (const float*)d_in[12];
    const float* fc2_w  = (const float*)d_in[13];
    const float* fc2_b  = (const float*)d_in[14];
    float* out = (float*)d_out;

    float *h, *qkv, *attnout, *xres, *mlp1;
    cudaGetSymbolAddress((void**)&h,       g_h);
    cudaGetSymbolAddress((void**)&qkv,     g_qkv);
    cudaGetSymbolAddress((void**)&attnout, g_attnout);
    cudaGetSymbolAddress((void**)&xres,    g_xres);
    cudaGetSymbolAddress((void**)&mlp1,    g_mlp1);

    // 1. h = LN1(x)
    ln_kernel<<<MROWS, 128>>>(x, n1_g, n1_b, h);
    // 2. qkv = h @ qkv_w + qkv_b        [8192, 1536]
    gemm_tc<EPI_BIAS><<<dim3(12, 64), 256>>>(h, qkv_w, qkv_b, nullptr, qkv,
                                             MROWS, 3 * DIM, DIM);
    // 3. expand rel-pos bias to [H, L, L]
    bias_expand_kernel<<<(HEADS * SEQ * SEQ) / 256, 256>>>(rel, table);
    // 4. flash attention (tensor cores) -> [B, L, C]
    attn_tc_kernel<<<dim3(8, HEADS, BATCH), 256>>>(attnout);
    // 5. xres = x + attnout @ proj_w + proj_b
    gemm_tc<EPI_RES><<<dim3(4, 64), 256>>>(attnout, proj_w, proj_b, x, xres,
                                           MROWS, DIM, DIM);
    // 6. h = LN2(xres)
    ln_kernel<<<MROWS, 128>>>(xres, n2_g, n2_b, h);
    // 7. mlp1 = gelu(h @ fc1_w + fc1_b)  [8192, 2048]
    gemm_tc<EPI_GELU><<<dim3(16, 64), 256>>>(h, fc1_w, fc1_b, nullptr, mlp1,
                                             MROWS, MLPH, DIM);
    // 8. out = xres + mlp1 @ fc2_w + fc2_b
    gemm_tc<EPI_RES><<<dim3(4, 64), 256>>>(mlp1, fc2_w, fc2_b, xres, out,
                                           MROWS, DIM, MLPH);
}

// round 6
// speedup vs baseline: 3.1254x; 1.1559x over previous
#include <cuda_runtime.h>
#include <math.h>
#include <stdint.h>

#define BATCH 8
#define SEQ 1024
#define DIM 512
#define HEADS 16
#define HD 32
#define MROWS (BATCH*SEQ)   /* 8192 */
#define MLPH 2048

// ---------------- scratch (device globals; no allocations allowed) ----------
__device__ float g_h[MROWS * DIM];           // LN out (tf32-rounded)
__device__ float g_qkv[MROWS * 3 * DIM];     // rounded q|k|v
__device__ float g_bias[HEADS * SEQ * SEQ];  // expanded rel-pos bias
__device__ float g_attnout[MROWS * DIM];     // rounded attention output
__device__ float g_xres[MROWS * DIM];        // x + proj(attn)  (fp32)
__device__ float g_mlp1[MROWS * MLPH];       // rounded gelu(fc1)
__device__ float g_w[3145728];               // rounded weights: qkv|proj|fc1|fc2

#define W_QKV  0
#define W_PROJ 786432
#define W_FC1  1048576
#define W_FC2  2097152

// ---------------- helpers ----------------------------------------------------
__device__ __forceinline__ float to_tf32(float x) {
    uint32_t u;
    asm("cvt.rna.tf32.f32 %0, %1;" : "=r"(u) : "f"(x));
    return __uint_as_float(u);
}

__device__ __forceinline__ void mma_tf32(float* c, const uint32_t* a,
                                         uint32_t b0, uint32_t b1) {
    asm volatile(
        "mma.sync.aligned.m16n8k8.row.col.f32.tf32.tf32.f32 "
        "{%0,%1,%2,%3}, {%4,%5,%6,%7}, {%8,%9}, {%0,%1,%2,%3};"
        : "+f"(c[0]), "+f"(c[1]), "+f"(c[2]), "+f"(c[3])
        : "r"(a[0]), "r"(a[1]), "r"(a[2]), "r"(a[3]), "r"(b0), "r"(b1));
}

__device__ __forceinline__ void cp16(uint32_t s, const void* g) {
    asm volatile("cp.async.cg.shared.global [%0], [%1], 16;\n" :: "r"(s), "l"(g));
}
__device__ __forceinline__ void cp_commit() {
    asm volatile("cp.async.commit_group;\n");
}
template <int N> __device__ __forceinline__ void cp_wait() {
    asm volatile("cp.async.wait_group %0;\n" :: "n"(N));
}

// ---------------- weight rounding: out = tf32(in) ---------------------------
__global__ void __launch_bounds__(256) cvt_kernel(const float4* __restrict__ in,
                                                  float4* __restrict__ out)
{
    const int i = blockIdx.x * 256 + threadIdx.x;
    float4 v = in[i];
    v.x = to_tf32(v.x); v.y = to_tf32(v.y);
    v.z = to_tf32(v.z); v.w = to_tf32(v.w);
    out[i] = v;
}

// ---------------- LayerNorm (tf32-rounded output) ---------------------------
__global__ void __launch_bounds__(128) ln_kernel(const float* __restrict__ x,
                                                 const float* __restrict__ g,
                                                 const float* __restrict__ b,
                                                 float* __restrict__ out)
{
    const int row = blockIdx.x;
    const int t = threadIdx.x;
    const float4 v = ((const float4*)(x + (size_t)row * DIM))[t];
    float s  = v.x + v.y + v.z + v.w;
    float s2 = v.x*v.x + v.y*v.y + v.z*v.z + v.w*v.w;
    #pragma unroll
    for (int o = 16; o > 0; o >>= 1) {
        s  += __shfl_xor_sync(0xffffffffu, s,  o);
        s2 += __shfl_xor_sync(0xffffffffu, s2, o);
    }
    __shared__ float rs[4], rs2[4];
    if ((t & 31) == 0) { rs[t >> 5] = s; rs2[t >> 5] = s2; }
    __syncthreads();
    s  = rs[0] + rs[1] + rs[2] + rs[3];
    s2 = rs2[0] + rs2[1] + rs2[2] + rs2[3];
    const float mean = s * (1.0f / DIM);
    const float var  = s2 * (1.0f / DIM) - mean * mean;
    const float inv  = rsqrtf(var + 1e-5f);
    const float4 gg = ((const float4*)g)[t];
    const float4 bb = ((const float4*)b)[t];
    float4 o4;
    o4.x = to_tf32((v.x - mean) * inv * gg.x + bb.x);
    o4.y = to_tf32((v.y - mean) * inv * gg.y + bb.y);
    o4.z = to_tf32((v.z - mean) * inv * gg.z + bb.z);
    o4.w = to_tf32((v.w - mean) * inv * gg.w + bb.w);
    ((float4*)(out + (size_t)row * DIM))[t] = o4;
}

// ---------------- bias expand ------------------------------------------------
__global__ void __launch_bounds__(256) bias_expand_kernel(const int* __restrict__ rel,
                                                          const float* __restrict__ table)
{
    const unsigned idx = blockIdx.x * 256u + threadIdx.x;
    const int m = idx & 1023;
    const int l = (idx >> 10) & 1023;
    const int h = idx >> 20;
    const int ri = rel[l * SEQ + m];
    g_bias[idx] = table[ri * HEADS + h];
}

// ---------------- tf32 tensor-core GEMM, 64x64 warp tiles, cp.async ----------
// 128x128 block tile, BK=32, 128 threads = 4 warps (2x2), warp tile 64x64.
// Inputs must already be tf32-rounded. 2-stage smem pipeline via cp.async.
enum { EPI_BIAS = 0, EPI_GELU = 1, EPI_RES = 2 };

template <int EPI, int CVT>
__global__ void __launch_bounds__(128) gemm_tc(const float* __restrict__ A,
                                               const float* __restrict__ W,
                                               const float* __restrict__ bias,
                                               const float* __restrict__ R,
                                               float* __restrict__ C,
                                               int M, int N, int K)
{
    __shared__ __align__(16) float As[2][128][36];
    __shared__ __align__(16) float Bs[2][32][136];

    const int bm = blockIdx.y * 128, bn = blockIdx.x * 128;
    const int tid = threadIdx.x;
    const int warp = tid >> 5, lane = tid & 31;
    const int wm = (warp >> 1) * 64, wn = (warp & 1) * 64;
    const int g = lane >> 2, t4 = lane & 3;

    // staging geometry (128 threads, 16B chunks):
    // A: row = (tid>>3) + i*16, col = (tid&7)*4, i<8
    // B: row = (tid>>5) + i*4,  col = (tid&31)*4, i<8
    const int ar = tid >> 3, ac = (tid & 7) * 4;
    const int br = tid >> 5, bc = (tid & 31) * 4;

    float acc[4][8][4];
    #pragma unroll
    for (int mi = 0; mi < 4; mi++)
        #pragma unroll
        for (int ni = 0; ni < 8; ni++)
            #pragma unroll
            for (int c = 0; c < 4; c++) acc[mi][ni][c] = 0.0f;

    const int nk = K >> 5;

    // prologue: stage 0
    {
        const float* Ap = A + (size_t)(bm + ar) * K + ac;
        uint32_t sa = (uint32_t)__cvta_generic_to_shared(&As[0][ar][ac]);
        #pragma unroll
        for (int i = 0; i < 8; i++)
            cp16(sa + i * 16 * 36 * 4, Ap + (size_t)i * 16 * K);
        const float* Wp = W + (size_t)br * N + bn + bc;
        uint32_t sb = (uint32_t)__cvta_generic_to_shared(&Bs[0][br][bc]);
        #pragma unroll
        for (int i = 0; i < 8; i++)
            cp16(sb + i * 4 * 136 * 4, Wp + (size_t)i * 4 * N);
        cp_commit();
    }

    for (int kt = 0; kt < nk; kt++) {
        const int s = kt & 1;
        if (kt + 1 < nk) {
            const int k0 = (kt + 1) * 32;
            const int sn = s ^ 1;
            const float* Ap = A + (size_t)(bm + ar) * K + k0 + ac;
            uint32_t sa = (uint32_t)__cvta_generic_to_shared(&As[sn][ar][ac]);
            #pragma unroll
            for (int i = 0; i < 8; i++)
                cp16(sa + i * 16 * 36 * 4, Ap + (size_t)i * 16 * K);
            const float* Wp = W + (size_t)(k0 + br) * N + bn + bc;
            uint32_t sb = (uint32_t)__cvta_generic_to_shared(&Bs[sn][br][bc]);
            #pragma unroll
            for (int i = 0; i < 8; i++)
                cp16(sb + i * 4 * 136 * 4, Wp + (size_t)i * 4 * N);
            cp_commit();
            cp_wait<1>();
        } else {
            cp_wait<0>();
        }
        __syncthreads();

        #pragma unroll
        for (int ks = 0; ks < 4; ks++) {
            const int kk = ks * 8;
            uint32_t af[4][4];
            #pragma unroll
            for (int mi = 0; mi < 4; mi++) {
                const int rm = wm + mi * 16;
                af[mi][0] = __float_as_uint(As[s][rm + g][kk + t4]);
                af[mi][1] = __float_as_uint(As[s][rm + g + 8][kk + t4]);
                af[mi][2] = __float_as_uint(As[s][rm + g][kk + t4 + 4]);
                af[mi][3] = __float_as_uint(As[s][rm + g + 8][kk + t4 + 4]);
            }
            #pragma unroll
            for (int ni = 0; ni < 8; ni++) {
                const int cn = wn + ni * 8 + g;
                const uint32_t b0 = __float_as_uint(Bs[s][kk + t4][cn]);
                const uint32_t b1 = __float_as_uint(Bs[s][kk + t4 + 4][cn]);
                #pragma unroll
                for (int mi = 0; mi < 4; mi++)
                    mma_tf32(acc[mi][ni], af[mi], b0, b1);
            }
        }
        __syncthreads();
    }

    // epilogue
    #pragma unroll
    for (int mi = 0; mi < 4; mi++) {
        const int r0 = bm + wm + mi * 16 + g;
        #pragma unroll
        for (int ni = 0; ni < 8; ni++) {
            const int col = bn + wn + ni * 8 + t4 * 2;
            const float b0 = bias[col], b1 = bias[col + 1];
            float v[4];
            v[0] = acc[mi][ni][0] + b0;
            v[1] = acc[mi][ni][1] + b1;
            v[2] = acc[mi][ni][2] + b0;
            v[3] = acc[mi][ni][3] + b1;
            if (EPI == EPI_GELU) {
                #pragma unroll
                for (int c = 0; c < 4; c++)
                    v[c] = 0.5f * v[c] * (1.0f + erff(v[c] * 0.70710678118654752f));
            }
            const size_t off0 = (size_t)r0 * N + col;
            const size_t off1 = (size_t)(r0 + 8) * N + col;
            if (EPI == EPI_RES) {
                const float2 r4a = *(const float2*)(R + off0);
                const float2 r4b = *(const float2*)(R + off1);
                v[0] += r4a.x; v[1] += r4a.y;
                v[2] += r4b.x; v[3] += r4b.y;
            }
            if (CVT) {
                #pragma unroll
                for (int c = 0; c < 4; c++) v[c] = to_tf32(v[c]);
            }
            *(float2*)(C + off0) = make_float2(v[0], v[1]);
            *(float2*)(C + off1) = make_float2(v[2], v[3]);
        }
    }
}

// ---------------- Flash attention on tensor cores (cp.async K/V) ------------
// Block: 128 queries x one (b,h); 8 warps, 16 query rows each; 64-key tiles.
__global__ void __launch_bounds__(256) attn_tc_kernel(float* __restrict__ out)
{
    __shared__ __align__(16) float Ks[2][64][36];
    __shared__ __align__(16) float Vs[2][64][36];
    __shared__ float Ps[8][16][68];

    const int b = blockIdx.z, h = blockIdx.y, q0 = blockIdx.x * 128;
    const int tid = threadIdx.x;
    const int warp = tid >> 5, lane = tid & 31;
    const int g = lane >> 2, t4 = lane & 3;
    const int wq = warp * 16;

    const float scale = 0.17677669529663687f; // 1/sqrt(32)

    // ---- Q fragments (inputs pre-rounded; re-round after scaling) ----
    uint32_t qf[4][4];
    {
        const float* q0p = g_qkv + ((size_t)(b * SEQ + q0 + wq + g)) * (3 * DIM) + h * HD;
        const float* q1p = q0p + 8 * (3 * DIM);
        #pragma unroll
        for (int ks = 0; ks < 4; ks++) {
            const int kk = ks * 8;
            qf[ks][0] = __float_as_uint(to_tf32(q0p[kk + t4] * scale));
            qf[ks][1] = __float_as_uint(to_tf32(q1p[kk + t4] * scale));
            qf[ks][2] = __float_as_uint(to_tf32(q0p[kk + t4 + 4] * scale));
            qf[ks][3] = __float_as_uint(to_tf32(q1p[kk + t4 + 4] * scale));
        }
    }

    float m0 = -1e30f, m1 = -1e30f, li0 = 0.0f, li1 = 0.0f;
    float acc_o[4][4];
    #pragma unroll
    for (int ni = 0; ni < 4; ni++)
        #pragma unroll
        for (int c = 0; c < 4; c++) acc_o[ni][c] = 0.0f;

    const float* bias0 = g_bias + ((size_t)h * SEQ + q0 + wq + g) * SEQ;
    const float* bias1 = bias0 + 8 * SEQ;

    // K/V staging: fid = tid + i*256 -> key = fid>>3, c4 = (fid&7)*4, i<2
    const int key0 = tid >> 3, c40 = (tid & 7) * 4;

    // prologue: stage tile 0
    {
        #pragma unroll
        for (int i = 0; i < 2; i++) {
            const int key = key0 + i * 32;
            const float* kp = g_qkv + ((size_t)(b * SEQ + key)) * (3 * DIM)
                              + DIM + h * HD + c40;
            cp16((uint32_t)__cvta_generic_to_shared(&Ks[0][key][c40]), kp);
            cp16((uint32_t)__cvta_generic_to_shared(&Vs[0][key][c40]), kp + DIM);
        }
        cp_commit();
    }

    for (int it = 0; it < SEQ / 64; it++) {
        const int s = it & 1;
        const int k0 = it * 64;
        if (it + 1 < SEQ / 64) {
            const int sn = s ^ 1;
            #pragma unroll
            for (int i = 0; i < 2; i++) {
                const int key = key0 + i * 32;
                const float* kp = g_qkv + ((size_t)(b * SEQ + k0 + 64 + key)) * (3 * DIM)
                                  + DIM + h * HD + c40;
                cp16((uint32_t)__cvta_generic_to_shared(&Ks[sn][key][c40]), kp);
                cp16((uint32_t)__cvta_generic_to_shared(&Vs[sn][key][c40]), kp + DIM);
            }
            cp_commit();
            cp_wait<1>();
        } else {
            cp_wait<0>();
        }
        __syncthreads();

        // ---- S = Q @ K^T ----
        float sacc[8][4];
        #pragma unroll
        for (int ni = 0; ni < 8; ni++)
            #pragma unroll
            for (int c = 0; c < 4; c++) sacc[ni][c] = 0.0f;
        #pragma unroll
        for (int ks = 0; ks < 4; ks++) {
            const int kk = ks * 8;
            #pragma unroll
            for (int ni = 0; ni < 8; ni++) {
                const uint32_t b0 = __float_as_uint(Ks[s][ni * 8 + g][kk + t4]);
                const uint32_t b1 = __float_as_uint(Ks[s][ni * 8 + g][kk + t4 + 4]);
                mma_tf32(sacc[ni], qf[ks], b0, b1);
            }
        }
        // ---- + bias ----
        #pragma unroll
        for (int ni = 0; ni < 8; ni++) {
            const int col = k0 + ni * 8 + t4 * 2;
            const float2 bv0 = *(const float2*)(bias0 + col);
            const float2 bv1 = *(const float2*)(bias1 + col);
            sacc[ni][0] += bv0.x; sacc[ni][1] += bv0.y;
            sacc[ni][2] += bv1.x; sacc[ni][3] += bv1.y;
        }

        // ---- online softmax ----
        float vmax0 = -1e30f, vmax1 = -1e30f;
        #pragma unroll
        for (int ni = 0; ni < 8; ni++) {
            vmax0 = fmaxf(vmax0, fmaxf(sacc[ni][0], sacc[ni][1]));
            vmax1 = fmaxf(vmax1, fmaxf(sacc[ni][2], sacc[ni][3]));
        }
        #pragma unroll
        for (int o = 1; o <= 2; o <<= 1) {
            vmax0 = fmaxf(vmax0, __shfl_xor_sync(0xffffffffu, vmax0, o));
            vmax1 = fmaxf(vmax1, __shfl_xor_sync(0xffffffffu, vmax1, o));
        }
        const float nm0 = fmaxf(m0, vmax0);
        const float nm1 = fmaxf(m1, vmax1);
        const float corr0 = __expf(m0 - nm0);
        const float corr1 = __expf(m1 - nm1);
        m0 = nm0; m1 = nm1;
        float rs0 = 0.0f, rs1 = 0.0f;

        __syncwarp();
        #pragma unroll
        for (int ni = 0; ni < 8; ni++) {
            const float p0 = __expf(sacc[ni][0] - m0);
            const float p1 = __expf(sacc[ni][1] - m0);
            const float p2 = __expf(sacc[ni][2] - m1);
            const float p3 = __expf(sacc[ni][3] - m1);
            rs0 += p0 + p1; rs1 += p2 + p3;
            const int col = ni * 8 + t4 * 2;
            *(float2*)&Ps[warp][g][col]     = make_float2(to_tf32(p0), to_tf32(p1));
            *(float2*)&Ps[warp][g + 8][col] = make_float2(to_tf32(p2), to_tf32(p3));
        }
        li0 = li0 * corr0 + rs0;
        li1 = li1 * corr1 + rs1;
        #pragma unroll
        for (int ni = 0; ni < 4; ni++) {
            acc_o[ni][0] *= corr0; acc_o[ni][1] *= corr0;
            acc_o[ni][2] *= corr1; acc_o[ni][3] *= corr1;
        }
        __syncwarp();

        // ---- O += P @ V ----
        #pragma unroll
        for (int ks = 0; ks < 8; ks++) {
            const int kk = ks * 8;
            uint32_t af[4];
            af[0] = __float_as_uint(Ps[warp][g][kk + t4]);
            af[1] = __float_as_uint(Ps[warp][g + 8][kk + t4]);
            af[2] = __float_as_uint(Ps[warp][g][kk + t4 + 4]);
            af[3] = __float_as_uint(Ps[warp][g + 8][kk + t4 + 4]);
            #pragma unroll
            for (int ni = 0; ni < 4; ni++) {
                const uint32_t b0 = __float_as_uint(Vs[s][kk + t4][ni * 8 + g]);
                const uint32_t b1 = __float_as_uint(Vs[s][kk + t4 + 4][ni * 8 + g]);
                mma_tf32(acc_o[ni], af, b0, b1);
            }
        }
        __syncthreads();
    }

    // ---- finalize (rounded output: feeds proj GEMM) ----
    #pragma unroll
    for (int o = 1; o <= 2; o <<= 1) {
        li0 += __shfl_xor_sync(0xffffffffu, li0, o);
        li1 += __shfl_xor_sync(0xffffffffu, li1, o);
    }
    const float inv0 = 1.0f / li0;
    const float inv1 = 1.0f / li1;
    float* o0p = out + ((size_t)(b * SEQ + q0 + wq + g)) * DIM + h * HD;
    float* o1p = o0p + 8 * DIM;
    #pragma unroll
    for (int ni = 0; ni < 4; ni++) {
        const int col = ni * 8 + t4 * 2;
        *(float2*)(o0p + col) = make_float2(to_tf32(acc_o[ni][0] * inv0),
                                            to_tf32(acc_o[ni][1] * inv0));
        *(float2*)(o1p + col) = make_float2(to_tf32(acc_o[ni][2] * inv1),
                                            to_tf32(acc_o[ni][3] * inv1));
    }
}

// ---------------- launch -----------------------------------------------------
extern "C" void kernel_launch(void* const* d_in, const int* in_sizes, int n_in,
                              void* d_out, int out_size)
{
    const float* x      = (const float*)d_in[0];
    const int*   rel    = (const int*)  d_in[1];
    const float* table  = (const float*)d_in[2];
    const float* qkv_w  = (const float*)d_in[3];
    const float* qkv_b  = (const float*)d_in[4];
    const float* proj_w = (const float*)d_in[5];
    const float* proj_b = (const float*)d_in[6];
    const float* n1_g   = (const float*)d_in[7];
    const float* n1_b   = (const float*)d_in[8];
    const float* n2_g   = (const float*)d_in[9];
    const float* n2_b   = (const float*)d_in[10];
    const float* fc1_w  = (const float*)d_in[11];
    const float* fc1_b  = (const float*)d_in[12];
    const float* fc2_w  = (const float*)d_in[13];
    const float* fc2_b  = (const float*)d_in[14];
    float* out = (float*)d_out;

    float *h, *qkv, *attnout, *xres, *mlp1, *w;
    cudaGetSymbolAddress((void**)&h,       g_h);
    cudaGetSymbolAddress((void**)&qkv,     g_qkv);
    cudaGetSymbolAddress((void**)&attnout, g_attnout);
    cudaGetSymbolAddress((void**)&xres,    g_xres);
    cudaGetSymbolAddress((void**)&mlp1,    g_mlp1);
    cudaGetSymbolAddress((void**)&w,       g_w);

    // 0. round weights to tf32 (scratch)
    cvt_kernel<<<DIM * 3 * DIM / 1024, 256>>>((const float4*)qkv_w,  (float4*)(w + W_QKV));
    cvt_kernel<<<DIM * DIM / 1024, 256>>>((const float4*)proj_w,     (float4*)(w + W_PROJ));
    cvt_kernel<<<DIM * MLPH / 1024, 256>>>((const float4*)fc1_w,     (float4*)(w + W_FC1));
    cvt_kernel<<<MLPH * DIM / 1024, 256>>>((const float4*)fc2_w,     (float4*)(w + W_FC2));
    // 1. h = LN1(x) (rounded)
    ln_kernel<<<MROWS, 128>>>(x, n1_g, n1_b, h);
    // 2. qkv = round(h @ qkv_w + qkv_b)
    gemm_tc<EPI_BIAS, 1><<<dim3(12, 64), 128>>>(h, w + W_QKV, qkv_b, nullptr, qkv,
                                                MROWS, 3 * DIM, DIM);
    // 3. expand rel-pos bias to [H, L, L]
    bias_expand_kernel<<<(HEADS * SEQ * SEQ) / 256, 256>>>(rel, table);
    // 4. flash attention -> rounded [B, L, C]
    attn_tc_kernel<<<dim3(8, HEADS, BATCH), 256>>>(attnout);
    // 5. xres = x + attnout @ proj_w + proj_b  (fp32)
    gemm_tc<EPI_RES, 0><<<dim3(4, 64), 128>>>(attnout, w + W_PROJ, proj_b, x, xres,
                                              MROWS, DIM, DIM);
    // 6. h = LN2(xres) (rounded)
    ln_kernel<<<MROWS, 128>>>(xres, n2_g, n2_b, h);
    // 7. mlp1 = round(gelu(h @ fc1_w + fc1_b))
    gemm_tc<EPI_GELU, 1><<<dim3(16, 64), 128>>>(h, w + W_FC1, fc1_b, nullptr, mlp1,
                                                MROWS, MLPH, DIM);
    // 8. out = xres + mlp1 @ fc2_w + fc2_b  (fp32)
    gemm_tc<EPI_RES, 0><<<dim3(4, 64), 128>>>(mlp1, w + W_FC2, fc2_b, xres, out,
                                              MROWS, DIM, MLPH);
}